// round 9
// baseline (speedup 1.0000x reference)
#include <cuda_runtime.h>
#include <cuda_bf16.h>
#include <cfloat>
#include <cstdint>

#define HIDDEN    1024
#define NUM_HEADS 16
#define HEAD_DIM  64
#define BATCH     32
#define PREV_LEN  4095
#define SEQ       4096
#define SCALING   0.125f

__device__ float g_q[BATCH * HIDDEN];
__device__ float g_k[BATCH * HIDDEN];
__device__ float g_v[BATCH * HIDDEN];
// unnormalized attention partials over the 4095 cached positions
__device__ float g_fm[BATCH * NUM_HEADS];
__device__ float g_fl[BATCH * NUM_HEADS];
__device__ float g_facc[BATCH * NUM_HEADS * HEAD_DIM];

__device__ __forceinline__ float dot4(float4 a, float4 b) {
    return a.x*b.x + a.y*b.y + a.z*b.z + a.w*b.w;
}

#define GEMM_SMEM (8 * 1024 * 4)

// ---------------------------------------------------------------------------
// Deep-prefetch GEMM (standalone q / oproj kernels).
// ---------------------------------------------------------------------------
__device__ __forceinline__ void gemm_prefetch(
    const float* __restrict__ W, int j0, int lane, float4* wa, float4* wb)
{
    const float* Wa = W + (size_t)j0 * 1024 + lane * 4;
    const float* Wb = Wa + 1024;
    #pragma unroll
    for (int it = 0; it < 8; it++) {
        wa[it] = *(const float4*)(Wa + it * 128);
        wb[it] = *(const float4*)(Wb + it * 128);
    }
}

__device__ __forceinline__ void gemm_core(
    const float4* wa, const float4* wb,
    const float* __restrict__ bias, float* __restrict__ out,
    float scale, int row0, int j0, const float* Xs)
{
    int lane = threadIdx.x & 31;

    float acc[16];
    #pragma unroll
    for (int i = 0; i < 16; i++) acc[i] = 0.f;

    #pragma unroll
    for (int it = 0; it < 8; it++) {
        const float* xb = Xs + it * 128 + lane * 4;
        #pragma unroll
        for (int r = 0; r < 8; r++) {
            float4 x4 = *(const float4*)(xb + (r << 10));
            acc[r]     += dot4(x4, wa[it]);
            acc[8 + r] += dot4(x4, wb[it]);
        }
    }

    #pragma unroll
    for (int i = 0; i < 16; i++)
        acc[i] += __shfl_xor_sync(0xffffffffu, acc[i], 16);
    #pragma unroll
    for (int off = 8; off; off >>= 1) {
        #pragma unroll
        for (int i = 0; i < off; i++) {
            bool hi = (lane & off) != 0;
            float z = hi ? acc[i] : acc[i + off];
            z = __shfl_xor_sync(0xffffffffu, z, off);
            acc[i] = (hi ? acc[i + off] : acc[i]) + z;
        }
    }

    if (lane < 16) {
        int c = lane >> 3, r = lane & 7;
        int j = j0 + c;
        out[(row0 + r) * 1024 + j] = (acc[0] + bias[j]) * scale;
    }
}

// Register-light GEMM for the kv branch of the fused kernel.
__device__ __forceinline__ void gemm_compute_lite(
    const float* __restrict__ W, const float* __restrict__ bias,
    float* __restrict__ out, float scale, int row0, int colblk,
    const float* Xs)
{
    int warp = threadIdx.x >> 5;
    int lane = threadIdx.x & 31;
    int j0 = colblk * 16 + warp * 2;

    const float* Wa = W + (size_t)j0 * 1024;
    const float* Wb = Wa + 1024;

    float acc[16];
    #pragma unroll
    for (int i = 0; i < 16; i++) acc[i] = 0.f;

    float4 wa = *(const float4*)(Wa + lane * 4);
    float4 wb = *(const float4*)(Wb + lane * 4);

    #pragma unroll
    for (int it = 0; it < 8; it++) {
        int k0 = it * 128 + lane * 4;
        float4 ca = wa, cb = wb;
        if (it < 7) {
            wa = *(const float4*)(Wa + k0 + 128);
            wb = *(const float4*)(Wb + k0 + 128);
        }
        const float* xb = Xs + k0;
        #pragma unroll
        for (int r = 0; r < 8; r++) {
            float4 x4 = *(const float4*)(xb + (r << 10));
            acc[r]     += dot4(x4, ca);
            acc[8 + r] += dot4(x4, cb);
        }
    }

    #pragma unroll
    for (int i = 0; i < 16; i++)
        acc[i] += __shfl_xor_sync(0xffffffffu, acc[i], 16);
    #pragma unroll
    for (int off = 8; off; off >>= 1) {
        #pragma unroll
        for (int i = 0; i < off; i++) {
            bool hi = (lane & off) != 0;
            float z = hi ? acc[i] : acc[i + off];
            z = __shfl_xor_sync(0xffffffffu, z, off);
            acc[i] = (hi ? acc[i + off] : acc[i]) + z;
        }
    }

    if (lane < 16) {
        int c = lane >> 3, r = lane & 7;
        int j = j0 + c;
        out[(row0 + r) * 1024 + j] = (acc[0] + bias[j]) * scale;
    }
}

__device__ __forceinline__ void gemm_stage_x(const float* __restrict__ X,
                                             int row0, float* Xs)
{
    const float4* X4 = (const float4*)(X + row0 * 1024);
    float4* Xs4 = (float4*)Xs;
    for (int idx = threadIdx.x; idx < 8 * 1024 / 4; idx += 256)
        Xs4[idx] = X4[idx];
    __syncthreads();
}

// q projection (gates attention): 256 blocks, deep prefetch
__global__ __launch_bounds__(256) void q_kernel(
    const float* __restrict__ Xq, const float* __restrict__ Wq,
    const float* __restrict__ bq, float* __restrict__ oq)
{
    extern __shared__ float Xs[];
    int rt = blockIdx.x >> 6;
    int cb = blockIdx.x & 63;
    int warp = threadIdx.x >> 5;
    int lane = threadIdx.x & 31;
    int j0 = cb * 16 + warp * 2;

    float4 wa[8], wb[8];
    gemm_prefetch(Wq, j0, lane, wa, wb);
    gemm_stage_x(Xq, rt * 8, Xs);
    gemm_core(wa, wb, bq, oq, SCALING, rt * 8, j0, Xs);
}

// ---------------------------------------------------------------------------
// Attention streaming core, templated on the number of simultaneous queries
// JP (block-uniform). j=0 accumulator in registers; j>=1 in smem (RMW).
// All shuffles execute unconditionally within uniform control flow.
// ---------------------------------------------------------------------------
template<int JP>
__device__ __forceinline__ void attn_stream(
    const float* __restrict__ Kc, const float* __restrict__ Vc,
    const float* s_mask, const float* s_q, float4* s_accx,
    int hw, int sl, float* mj, float* lj, float4& a0)
{
    float4 q[JP];
    #pragma unroll
    for (int j = 0; j < JP; j++)
        q[j] = *(const float4*)(s_q + j * 64 + sl * 4);

    float4* ax = s_accx + hw * 16 + sl;

    #pragma unroll 4
    for (int it = 0; it < 255; it++) {
        int s = (it << 4) + hw;
        float4 k4 = *(const float4*)(Kc + (size_t)s * HEAD_DIM + sl * 4);
        float4 v4 = *(const float4*)(Vc + (size_t)s * HEAD_DIM + sl * 4);
        float maskv = s_mask[s];

        #pragma unroll
        for (int j = 0; j < JP; j++) {
            float p = dot4(q[j], k4);
            p += __shfl_xor_sync(0xffffffffu, p, 8);
            p += __shfl_xor_sync(0xffffffffu, p, 4);
            p += __shfl_xor_sync(0xffffffffu, p, 2);
            p += __shfl_xor_sync(0xffffffffu, p, 1);

            float score = p - maskv;
            float nm = fmaxf(mj[j], score);
            float es = __expf(mj[j] - nm);
            float w  = __expf(score - nm);
            lj[j] = lj[j] * es + w;
            if (j == 0) {
                a0.x = a0.x * es + w * v4.x;
                a0.y = a0.y * es + w * v4.y;
                a0.z = a0.z * es + w * v4.z;
                a0.w = a0.w * es + w * v4.w;
            } else {
                float4 a = ax[(j - 1) * 256];
                a.x = a.x * es + w * v4.x;
                a.y = a.y * es + w * v4.y;
                a.z = a.z * es + w * v4.z;
                a.w = a.w * es + w * v4.w;
                ax[(j - 1) * 256] = a;
            }
            mj[j] = nm;
        }
    }

    // tail iteration: s = 4080 + hw; hw==15 (s=4095) excluded.
    {
        int s = (255 << 4) + hw;
        bool valid = s < PREV_LEN;
        int sc = valid ? s : 0;
        float4 k4 = *(const float4*)(Kc + (size_t)sc * HEAD_DIM + sl * 4);
        float4 v4 = *(const float4*)(Vc + (size_t)sc * HEAD_DIM + sl * 4);
        float maskv = s_mask[s];

        #pragma unroll
        for (int j = 0; j < JP; j++) {
            float p = dot4(q[j], k4);
            p += __shfl_xor_sync(0xffffffffu, p, 8);
            p += __shfl_xor_sync(0xffffffffu, p, 4);
            p += __shfl_xor_sync(0xffffffffu, p, 2);
            p += __shfl_xor_sync(0xffffffffu, p, 1);

            if (valid) {
                float score = p - maskv;
                float nm = fmaxf(mj[j], score);
                float es = __expf(mj[j] - nm);
                float w  = __expf(score - nm);
                lj[j] = lj[j] * es + w;
                if (j == 0) {
                    a0.x = a0.x * es + w * v4.x;
                    a0.y = a0.y * es + w * v4.y;
                    a0.z = a0.z * es + w * v4.z;
                    a0.w = a0.w * es + w * v4.w;
                } else {
                    float4 a = ax[(j - 1) * 256];
                    a.x = a.x * es + w * v4.x;
                    a.y = a.y * es + w * v4.y;
                    a.z = a.z * es + w * v4.z;
                    a.w = a.w * es + w * v4.w;
                    ax[(j - 1) * 256] = a;
                }
                mj[j] = nm;
            }
        }
    }
}

__device__ __forceinline__ void attn_combine(
    const float4* src, const float* s_m, const float* s_l, int tid, int nout)
{
    if (tid < HEAD_DIM) {
        float M = s_m[0];
        #pragma unroll
        for (int w = 1; w < 16; w++) M = fmaxf(M, s_m[w]);
        float L = 0.f, A = 0.f;
        #pragma unroll
        for (int w = 0; w < 16; w++) {
            float f = __expf(s_m[w] - M);
            L += s_l[w] * f;
            A += ((const float*)(src + w * 16))[tid] * f;
        }
        g_facc[nout * HEAD_DIM + tid] = A;
        if (tid == 0) { g_fm[nout] = M; g_fl[nout] = L; }
    }
}

// ---------------------------------------------------------------------------
// Fused kernel. Blocks 0..511: attention, parallelized over CACHE SLOTS
// (c, h). Each block streams slot c's K/V exactly once from DRAM and
// computes online-softmax for every b with order[b]==c (up to 4 per pass).
// Slots with no consumer exit immediately -> their DRAM traffic vanishes.
// Blocks 512..1023: k/v projection GEMM backfill.
// ---------------------------------------------------------------------------
__global__ __launch_bounds__(256) void attn_kv_kernel(
    const float* __restrict__ prev_key, const float* __restrict__ prev_value,
    const int*  __restrict__ order,     const int* __restrict__ mask,
    const float* __restrict__ Xk, const float* __restrict__ Xv,
    const float* __restrict__ Wk, const float* __restrict__ bk,
    const float* __restrict__ Wv, const float* __restrict__ bv,
    float* __restrict__ ok, float* __restrict__ ov)
{
    extern __shared__ float smemBuf[];

    if (blockIdx.x >= 512) {
        int blk = blockIdx.x - 512;       // p*256 + rt*64 + cb
        int p   = blk >> 8;
        int rt  = (blk >> 6) & 3;
        int cb  = blk & 63;
        if (p == 0) {
            gemm_stage_x(Xk, rt * 8, smemBuf);
            gemm_compute_lite(Wk, bk, ok, 1.0f, rt * 8, cb, smemBuf);
        } else {
            gemm_stage_x(Xv, rt * 8, smemBuf);
            gemm_compute_lite(Wv, bv, ov, 1.0f, rt * 8, cb, smemBuf);
        }
        return;
    }

    // ---- attention block for cache slot c, head h ----
    int tid = threadIdx.x;
    int hw  = tid >> 4;
    int sl  = tid & 15;
    int c   = blockIdx.x >> 4;
    int h   = blockIdx.x & 15;

    __shared__ int s_matches[BATCH];
    __shared__ int s_jcount;
    if (tid == 0) {
        int jc = 0;
        for (int b2 = 0; b2 < BATCH; b2++)
            if (order[b2] == c) s_matches[jc++] = b2;
        s_jcount = jc;
    }
    __syncthreads();
    int jcount = s_jcount;
    if (jcount == 0) return;            // nobody consumes this slot

    // smem layout inside dynamic buffer (floats):
    // [0,4096)  mask   (reused as jj=0 combine staging after hot loop)
    // [4096..)  s_m[16], s_l[16], s_q[256], accx (3*256 float4, 16B aligned)
    float*  s_mask  = smemBuf;
    float*  s_m     = smemBuf + 4096;
    float*  s_l     = smemBuf + 4112;
    float*  s_q     = smemBuf + 4128;
    float4* s_accx  = (float4*)(smemBuf + 4384);
    float4* s_stage = (float4*)smemBuf;   // aliases mask region

    size_t cache_base = ((size_t)(c * NUM_HEADS + h)) * PREV_LEN * HEAD_DIM;
    const float* Kc = prev_key   + cache_base;
    const float* Vc = prev_value + cache_base;

    for (int base = 0; base < jcount; base += 4) {
        int jpass = jcount - base;
        if (jpass > 4) jpass = 4;

        // stage mask (clobbered by previous pass's combine staging)
        for (int idx = tid; idx < SEQ; idx += 256)
            s_mask[idx] = FLT_MAX * (float)mask[idx];
        // stage q rows (zeros beyond jpass)
        {
            int jj = tid >> 6, d = tid & 63;
            float val = 0.f;
            if (jj < jpass)
                val = g_q[s_matches[base + jj] * HIDDEN + h * HEAD_DIM + d];
            s_q[jj * 64 + d] = val;
        }
        // zero smem accumulators
        for (int i = tid; i < 3 * 256; i += 256)
            s_accx[i] = make_float4(0.f, 0.f, 0.f, 0.f);
        __syncthreads();

        float mj[4] = { -FLT_MAX, -FLT_MAX, -FLT_MAX, -FLT_MAX };
        float lj[4] = { 0.f, 0.f, 0.f, 0.f };
        float4 a0 = make_float4(0.f, 0.f, 0.f, 0.f);

        switch (jpass) {
        case 1: attn_stream<1>(Kc, Vc, s_mask, s_q, s_accx, hw, sl, mj, lj, a0); break;
        case 2: attn_stream<2>(Kc, Vc, s_mask, s_q, s_accx, hw, sl, mj, lj, a0); break;
        case 3: attn_stream<3>(Kc, Vc, s_mask, s_q, s_accx, hw, sl, mj, lj, a0); break;
        default: attn_stream<4>(Kc, Vc, s_mask, s_q, s_accx, hw, sl, mj, lj, a0); break;
        }

        // combine jj=0 (regs -> staging area overlapping dead mask)
        s_stage[hw * 16 + sl] = a0;
        if (sl == 0) { s_m[hw] = mj[0]; s_l[hw] = lj[0]; }
        __syncthreads();
        attn_combine(s_stage, s_m, s_l, tid, s_matches[base] * NUM_HEADS + h);
        __syncthreads();

        // combine jj=1..3 (accumulators already in smem)
        #pragma unroll
        for (int jj = 1; jj < 4; jj++) {
            if (jj < jpass) {
                if (sl == 0) { s_m[hw] = mj[jj]; s_l[hw] = lj[jj]; }
                __syncthreads();
                attn_combine(s_accx + (jj - 1) * 256, s_m, s_l, tid,
                             s_matches[base + jj] * NUM_HEADS + h);
                __syncthreads();
            }
        }
    }
}

// ---------------------------------------------------------------------------
// oproj + fused fresh-position merge, deep-prefetch GEMM.  256 blocks.
// ---------------------------------------------------------------------------
__global__ __launch_bounds__(256) void oproj_merge_kernel(
    const int* __restrict__ mask,
    const float* __restrict__ W, const float* __restrict__ bias,
    float* __restrict__ out)
{
    extern __shared__ float Xs[];
    __shared__ float s_es[8 * 16];
    __shared__ float s_w [8 * 16];

    int rt = blockIdx.x >> 6;
    int cb = blockIdx.x & 63;
    int row0 = rt * 8;
    int tid = threadIdx.x;
    int warp = tid >> 5;
    int lane = tid & 31;
    int j0 = cb * 16 + warp * 2;

    float4 wa[8], wb[8];
    gemm_prefetch(W, j0, lane, wa, wb);

    if (tid < 128) {
        int r = tid >> 4, h = tid & 15;
        int b = row0 + r;
        int n = b * NUM_HEADS + h;
        int qbase = b * HIDDEN + h * HEAD_DIM;

        float p = 0.f;
        #pragma unroll
        for (int i = 0; i < HEAD_DIM; i += 4) {
            float4 qq = *(const float4*)(g_q + qbase + i);   // pre-scaled
            float4 kk = *(const float4*)(g_k + qbase + i);
            p += dot4(qq, kk);
        }
        float score = p - FLT_MAX * (float)mask[PREV_LEN];
        float m = g_fm[n], l = g_fl[n];
        float nm = fmaxf(m, score);
        float es = __expf(m - nm);
        float w  = __expf(score - nm);
        float L  = l * es + w;
        s_es[tid] = es / L;
        s_w[tid]  = w  / L;
    }
    __syncthreads();

    for (int idx4 = tid; idx4 < 8 * 256; idx4 += 256) {
        int r    = idx4 >> 8;
        int c4   = idx4 & 255;
        int h    = c4 >> 4;
        int rh   = r * 16 + h;
        float esL = s_es[rh], wL = s_w[rh];
        int b = row0 + r;
        int n = b * NUM_HEADS + h;
        int d4 = c4 & 15;
        float4 fa = *(const float4*)(g_facc + n * HEAD_DIM + d4 * 4);
        float4 vv = *(const float4*)(g_v + b * HIDDEN + c4 * 4);
        float4 x;
        x.x = fa.x * esL + vv.x * wL;
        x.y = fa.y * esL + vv.y * wL;
        x.z = fa.z * esL + vv.z * wL;
        x.w = fa.w * esL + vv.w * wL;
        ((float4*)Xs)[idx4] = x;
    }
    __syncthreads();

    gemm_core(wa, wb, bias, out, 1.0f, row0, j0, Xs);
}

// ---------------------------------------------------------------------------
extern "C" void kernel_launch(void* const* d_in, const int* in_sizes, int n_in,
                              void* d_out, int out_size)
{
    const float* qin  = (const float*)d_in[0];
    const float* kin  = (const float*)d_in[1];
    const float* vin  = (const float*)d_in[2];
    const int*   mask = (const int*)  d_in[3];
    const int*   ord  = (const int*)  d_in[4];
    const float* pk   = (const float*)d_in[5];
    const float* pv   = (const float*)d_in[6];
    const float* Wq   = (const float*)d_in[7];
    const float* bq   = (const float*)d_in[8];
    const float* Wk   = (const float*)d_in[9];
    const float* bk   = (const float*)d_in[10];
    const float* Wv   = (const float*)d_in[11];
    const float* bv   = (const float*)d_in[12];
    const float* Wo   = (const float*)d_in[13];
    const float* bo   = (const float*)d_in[14];
    float* out = (float*)d_out;

    float *gq, *gk, *gv;
    cudaGetSymbolAddress((void**)&gq, g_q);
    cudaGetSymbolAddress((void**)&gk, g_k);
    cudaGetSymbolAddress((void**)&gv, g_v);

    q_kernel<<<256, 256, GEMM_SMEM>>>(qin, Wq, bq, gq);
    attn_kv_kernel<<<1024, 256, GEMM_SMEM>>>(pk, pv, ord, mask,
                                             kin, vin, Wk, bk, Wv, bv, gk, gv);
    oproj_merge_kernel<<<256, 256, GEMM_SMEM>>>(mask, Wo, bo, out);
}

// round 10
// speedup vs baseline: 1.2136x; 1.2136x over previous
#include <cuda_runtime.h>
#include <cuda_bf16.h>
#include <cfloat>
#include <cstdint>

#define HIDDEN    1024
#define NUM_HEADS 16
#define HEAD_DIM  64
#define BATCH     32
#define PREV_LEN  4095
#define SEQ       4096
#define SCALING   0.125f

__device__ float g_q[BATCH * HIDDEN];
__device__ float g_k[BATCH * HIDDEN];
__device__ float g_v[BATCH * HIDDEN];
// unnormalized attention partials over the 4095 cached positions
__device__ float g_fm[BATCH * NUM_HEADS];
__device__ float g_fl[BATCH * NUM_HEADS];
__device__ float g_facc[BATCH * NUM_HEADS * HEAD_DIM];

__device__ __forceinline__ float dot4(float4 a, float4 b) {
    return a.x*b.x + a.y*b.y + a.z*b.z + a.w*b.w;
}

#define GEMM_SMEM (8 * 1024 * 4)

// ---------------------------------------------------------------------------
// Deep-prefetch GEMM (standalone q / oproj kernels):
// all 8 W chunks for both columns issued up-front (16 LDG.128, MLP=16).
// ---------------------------------------------------------------------------
__device__ __forceinline__ void gemm_prefetch(
    const float* __restrict__ W, int j0, int lane, float4* wa, float4* wb)
{
    const float* Wa = W + (size_t)j0 * 1024 + lane * 4;
    const float* Wb = Wa + 1024;
    #pragma unroll
    for (int it = 0; it < 8; it++) {
        wa[it] = *(const float4*)(Wa + it * 128);
        wb[it] = *(const float4*)(Wb + it * 128);
    }
}

__device__ __forceinline__ void gemm_core(
    const float4* wa, const float4* wb,
    const float* __restrict__ bias, float* __restrict__ out,
    float scale, int row0, int j0, const float* Xs)
{
    int lane = threadIdx.x & 31;

    float acc[16];
    #pragma unroll
    for (int i = 0; i < 16; i++) acc[i] = 0.f;

    #pragma unroll
    for (int it = 0; it < 8; it++) {
        const float* xb = Xs + it * 128 + lane * 4;
        #pragma unroll
        for (int r = 0; r < 8; r++) {
            float4 x4 = *(const float4*)(xb + (r << 10));
            acc[r]     += dot4(x4, wa[it]);
            acc[8 + r] += dot4(x4, wb[it]);
        }
    }

    #pragma unroll
    for (int i = 0; i < 16; i++)
        acc[i] += __shfl_xor_sync(0xffffffffu, acc[i], 16);
    #pragma unroll
    for (int off = 8; off; off >>= 1) {
        #pragma unroll
        for (int i = 0; i < off; i++) {
            bool hi = (lane & off) != 0;
            float z = hi ? acc[i] : acc[i + off];
            z = __shfl_xor_sync(0xffffffffu, z, off);
            acc[i] = (hi ? acc[i + off] : acc[i]) + z;
        }
    }

    if (lane < 16) {
        int c = lane >> 3, r = lane & 7;
        int j = j0 + c;
        out[(row0 + r) * 1024 + j] = (acc[0] + bias[j]) * scale;
    }
}

// Register-light GEMM for the kv branch of the fused kernel.
__device__ __forceinline__ void gemm_compute_lite(
    const float* __restrict__ W, const float* __restrict__ bias,
    float* __restrict__ out, float scale, int row0, int colblk,
    const float* Xs)
{
    int warp = threadIdx.x >> 5;
    int lane = threadIdx.x & 31;
    int j0 = colblk * 16 + warp * 2;

    const float* Wa = W + (size_t)j0 * 1024;
    const float* Wb = Wa + 1024;

    float acc[16];
    #pragma unroll
    for (int i = 0; i < 16; i++) acc[i] = 0.f;

    float4 wa = *(const float4*)(Wa + lane * 4);
    float4 wb = *(const float4*)(Wb + lane * 4);

    #pragma unroll
    for (int it = 0; it < 8; it++) {
        int k0 = it * 128 + lane * 4;
        float4 ca = wa, cb = wb;
        if (it < 7) {
            wa = *(const float4*)(Wa + k0 + 128);
            wb = *(const float4*)(Wb + k0 + 128);
        }
        const float* xb = Xs + k0;
        #pragma unroll
        for (int r = 0; r < 8; r++) {
            float4 x4 = *(const float4*)(xb + (r << 10));
            acc[r]     += dot4(x4, ca);
            acc[8 + r] += dot4(x4, cb);
        }
    }

    #pragma unroll
    for (int i = 0; i < 16; i++)
        acc[i] += __shfl_xor_sync(0xffffffffu, acc[i], 16);
    #pragma unroll
    for (int off = 8; off; off >>= 1) {
        #pragma unroll
        for (int i = 0; i < off; i++) {
            bool hi = (lane & off) != 0;
            float z = hi ? acc[i] : acc[i + off];
            z = __shfl_xor_sync(0xffffffffu, z, off);
            acc[i] = (hi ? acc[i + off] : acc[i]) + z;
        }
    }

    if (lane < 16) {
        int c = lane >> 3, r = lane & 7;
        int j = j0 + c;
        out[(row0 + r) * 1024 + j] = (acc[0] + bias[j]) * scale;
    }
}

__device__ __forceinline__ void gemm_stage_x(const float* __restrict__ X,
                                             int row0, float* Xs)
{
    const float4* X4 = (const float4*)(X + row0 * 1024);
    float4* Xs4 = (float4*)Xs;
    for (int idx = threadIdx.x; idx < 8 * 1024 / 4; idx += 256)
        Xs4[idx] = X4[idx];
    __syncthreads();
}

// q projection (gates attention): 256 blocks, deep prefetch
__global__ __launch_bounds__(256) void q_kernel(
    const float* __restrict__ Xq, const float* __restrict__ Wq,
    const float* __restrict__ bq, float* __restrict__ oq)
{
    extern __shared__ float Xs[];
    int rt = blockIdx.x >> 6;
    int cb = blockIdx.x & 63;
    int warp = threadIdx.x >> 5;
    int lane = threadIdx.x & 31;
    int j0 = cb * 16 + warp * 2;

    float4 wa[8], wb[8];
    gemm_prefetch(Wq, j0, lane, wa, wb);
    gemm_stage_x(Xq, rt * 8, Xs);
    gemm_core(wa, wb, bq, oq, SCALING, rt * 8, j0, Xs);
}

// ---------------------------------------------------------------------------
// Fused kernel: blocks 0..511 = attention over cached positions (critical
// path); blocks 512..1023 = k/v projection GEMM backfill.
// ---------------------------------------------------------------------------
__global__ __launch_bounds__(256) void attn_kv_kernel(
    const float* __restrict__ prev_key, const float* __restrict__ prev_value,
    const int*  __restrict__ order,     const int* __restrict__ mask,
    const float* __restrict__ Xk, const float* __restrict__ Xv,
    const float* __restrict__ Wk, const float* __restrict__ bk,
    const float* __restrict__ Wv, const float* __restrict__ bv,
    float* __restrict__ ok, float* __restrict__ ov)
{
    extern __shared__ float smemBuf[];

    if (blockIdx.x >= 512) {
        int blk = blockIdx.x - 512;       // p*256 + rt*64 + cb
        int p   = blk >> 8;
        int rt  = (blk >> 6) & 3;
        int cb  = blk & 63;
        if (p == 0) {
            gemm_stage_x(Xk, rt * 8, smemBuf);
            gemm_compute_lite(Wk, bk, ok, 1.0f, rt * 8, cb, smemBuf);
        } else {
            gemm_stage_x(Xv, rt * 8, smemBuf);
            gemm_compute_lite(Wv, bv, ov, 1.0f, rt * 8, cb, smemBuf);
        }
        return;
    }

    // ---- attention blocks ----
    float* s_mask = smemBuf;                       // [4096]
    float* s_m    = smemBuf + SEQ;                 // [16]
    float* s_l    = s_m + 16;                      // [16]
    float4* s_acc = (float4*)(s_l + 16);           // [16][16]

    int tid = threadIdx.x;
    int hw  = tid >> 4;
    int sl  = tid & 15;

    int n = blockIdx.x;
    int b = n >> 4;
    int h = n & 15;

    for (int idx = tid; idx < SEQ; idx += 256)
        s_mask[idx] = FLT_MAX * (float)mask[idx];
    __syncthreads();

    int ob = order[b];
    size_t cache_base = ((size_t)(ob * NUM_HEADS + h)) * PREV_LEN * HEAD_DIM;
    const float* Kc = prev_key   + cache_base;
    const float* Vc = prev_value + cache_base;

    int qbase = b * HIDDEN + h * HEAD_DIM;
    float4 q4 = *(const float4*)(g_q + qbase + sl * 4);

    float m = -FLT_MAX, l = 0.f;
    float4 acc = make_float4(0.f, 0.f, 0.f, 0.f);

    // iterations 0..254: s = 16*it + hw <= 4079 < 4095, always in bounds.
    // Deep unroll (8): ptxas front-batches ~16 LDG.128 per warp -> ~2x MLP,
    // pushing in-flight bytes/SM past the latency-bandwidth product.
    #pragma unroll 8
    for (int it = 0; it < 255; it++) {
        int s = (it << 4) + hw;
        const float* kp = Kc + (size_t)s * HEAD_DIM + sl * 4;
        const float* vp = Vc + (size_t)s * HEAD_DIM + sl * 4;
        float4 k4 = *(const float4*)kp;
        float4 v4 = *(const float4*)vp;

        float p = dot4(q4, k4);
        p += __shfl_xor_sync(0xffffffffu, p, 8);
        p += __shfl_xor_sync(0xffffffffu, p, 4);
        p += __shfl_xor_sync(0xffffffffu, p, 2);
        p += __shfl_xor_sync(0xffffffffu, p, 1);

        float score = p - s_mask[s];
        float nm = fmaxf(m, score);
        float es = __expf(m - nm);
        float w  = __expf(score - nm);
        l = l * es + w;
        acc.x = acc.x * es + w * v4.x;
        acc.y = acc.y * es + w * v4.y;
        acc.z = acc.z * es + w * v4.z;
        acc.w = acc.w * es + w * v4.w;
        m = nm;
    }

    // final iteration it=255: hw==15 (s=4095) out of range; all threads run
    // the shuffles (warp-converged), invalid lanes don't accumulate.
    {
        int s = (255 << 4) + hw;
        bool valid = s < PREV_LEN;
        int sc = valid ? s : 0;
        const float* kp = Kc + (size_t)sc * HEAD_DIM + sl * 4;
        const float* vp = Vc + (size_t)sc * HEAD_DIM + sl * 4;
        float4 k4 = *(const float4*)kp;
        float4 v4 = *(const float4*)vp;

        float p = dot4(q4, k4);
        p += __shfl_xor_sync(0xffffffffu, p, 8);
        p += __shfl_xor_sync(0xffffffffu, p, 4);
        p += __shfl_xor_sync(0xffffffffu, p, 2);
        p += __shfl_xor_sync(0xffffffffu, p, 1);

        if (valid) {
            float score = p - s_mask[s];
            float nm = fmaxf(m, score);
            float es = __expf(m - nm);
            float w  = __expf(score - nm);
            l = l * es + w;
            acc.x = acc.x * es + w * v4.x;
            acc.y = acc.y * es + w * v4.y;
            acc.z = acc.z * es + w * v4.z;
            acc.w = acc.w * es + w * v4.w;
            m = nm;
        }
    }

    s_acc[hw * 16 + sl] = acc;
    if (sl == 0) { s_m[hw] = m; s_l[hw] = l; }
    __syncthreads();

    if (tid < HEAD_DIM) {
        float M = s_m[0];
        #pragma unroll
        for (int w = 1; w < 16; w++) M = fmaxf(M, s_m[w]);
        float L = 0.f, A = 0.f;
        #pragma unroll
        for (int w = 0; w < 16; w++) {
            float f = __expf(s_m[w] - M);
            L += s_l[w] * f;
            A += ((const float*)(s_acc + w * 16))[tid] * f;
        }
        g_facc[n * HEAD_DIM + tid] = A;
        if (tid == 0) { g_fm[n] = M; g_fl[n] = L; }
    }
}

// ---------------------------------------------------------------------------
// oproj + fused fresh-position merge, deep-prefetch GEMM.  256 blocks.
// ---------------------------------------------------------------------------
__global__ __launch_bounds__(256) void oproj_merge_kernel(
    const int* __restrict__ mask,
    const float* __restrict__ W, const float* __restrict__ bias,
    float* __restrict__ out)
{
    extern __shared__ float Xs[];
    __shared__ float s_es[8 * 16];
    __shared__ float s_w [8 * 16];

    int rt = blockIdx.x >> 6;
    int cb = blockIdx.x & 63;
    int row0 = rt * 8;
    int tid = threadIdx.x;
    int warp = tid >> 5;
    int lane = tid & 31;
    int j0 = cb * 16 + warp * 2;

    float4 wa[8], wb[8];
    gemm_prefetch(W, j0, lane, wa, wb);

    if (tid < 128) {
        int r = tid >> 4, h = tid & 15;
        int b = row0 + r;
        int n = b * NUM_HEADS + h;
        int qbase = b * HIDDEN + h * HEAD_DIM;

        float p = 0.f;
        #pragma unroll
        for (int i = 0; i < HEAD_DIM; i += 4) {
            float4 qq = *(const float4*)(g_q + qbase + i);   // pre-scaled
            float4 kk = *(const float4*)(g_k + qbase + i);
            p += dot4(qq, kk);
        }
        float score = p - FLT_MAX * (float)mask[PREV_LEN];
        float m = g_fm[n], l = g_fl[n];
        float nm = fmaxf(m, score);
        float es = __expf(m - nm);
        float w  = __expf(score - nm);
        float L  = l * es + w;
        s_es[tid] = es / L;
        s_w[tid]  = w  / L;
    }
    __syncthreads();

    for (int idx4 = tid; idx4 < 8 * 256; idx4 += 256) {
        int r    = idx4 >> 8;
        int c4   = idx4 & 255;
        int h    = c4 >> 4;
        int rh   = r * 16 + h;
        float esL = s_es[rh], wL = s_w[rh];
        int b = row0 + r;
        int n = b * NUM_HEADS + h;
        int d4 = c4 & 15;
        float4 fa = *(const float4*)(g_facc + n * HEAD_DIM + d4 * 4);
        float4 vv = *(const float4*)(g_v + b * HIDDEN + c4 * 4);
        float4 x;
        x.x = fa.x * esL + vv.x * wL;
        x.y = fa.y * esL + vv.y * wL;
        x.z = fa.z * esL + vv.z * wL;
        x.w = fa.w * esL + vv.w * wL;
        ((float4*)Xs)[idx4] = x;
    }
    __syncthreads();

    gemm_core(wa, wb, bias, out, 1.0f, row0, j0, Xs);
}

// ---------------------------------------------------------------------------
extern "C" void kernel_launch(void* const* d_in, const int* in_sizes, int n_in,
                              void* d_out, int out_size)
{
    const float* qin  = (const float*)d_in[0];
    const float* kin  = (const float*)d_in[1];
    const float* vin  = (const float*)d_in[2];
    const int*   mask = (const int*)  d_in[3];
    const int*   ord  = (const int*)  d_in[4];
    const float* pk   = (const float*)d_in[5];
    const float* pv   = (const float*)d_in[6];
    const float* Wq   = (const float*)d_in[7];
    const float* bq   = (const float*)d_in[8];
    const float* Wk   = (const float*)d_in[9];
    const float* bk   = (const float*)d_in[10];
    const float* Wv   = (const float*)d_in[11];
    const float* bv   = (const float*)d_in[12];
    const float* Wo   = (const float*)d_in[13];
    const float* bo   = (const float*)d_in[14];
    float* out = (float*)d_out;

    float *gq, *gk, *gv;
    cudaGetSymbolAddress((void**)&gq, g_q);
    cudaGetSymbolAddress((void**)&gk, g_k);
    cudaGetSymbolAddress((void**)&gv, g_v);

    q_kernel<<<256, 256, GEMM_SMEM>>>(qin, Wq, bq, gq);
    attn_kv_kernel<<<1024, 256, GEMM_SMEM>>>(pk, pv, ord, mask,
                                             kin, vin, Wk, bk, Wv, bv, gk, gv);
    oproj_merge_kernel<<<256, 256, GEMM_SMEM>>>(mask, Wo, bo, out);
}